// round 14
// baseline (speedup 1.0000x reference)
#include <cuda_runtime.h>

// Problem constants
#define GAMMA 0.1f
#define TAU   0.01f
#define NN    256          // neuron count
#define MM    512          // astrocyte count
#define KK    512          // input dim
#define NN2   (NN * NN)    // 65536
#define SPLIT 8            // chunks per H row (32 KB each)
#define CHUNK (NN2 / SPLIT) // 8192 floats per chunk

#define SETUP_BLKS 32
#define D_ROWS_PER_BLK 16

// Kernel 1: setup + minimal slice of D (phi-free partial) to hide setup
#define PRE_D_BLKS  512
#define PRE_D_ROWS  (PRE_D_BLKS * D_ROWS_PER_BLK)   // 8192
#define KPRE_BLKS   (SETUP_BLKS + PRE_D_BLKS)       // 544

// Kernel 2: fixup first, then H contiguous, then remaining D contiguous
#define FIX_BLKS    (PRE_D_ROWS / (256 * 4))         // 8
#define H_BLKS      (MM * SPLIT)                     // 4096
#define MAIN_D_BLKS ((NN2 - PRE_D_ROWS) / D_ROWS_PER_BLK)  // 3584
#define H_START     FIX_BLKS                         // 8
#define D_START     (FIX_BLKS + H_BLKS)              // 4104
#define KMAIN_BLKS  (FIX_BLKS + H_BLKS + MAIN_D_BLKS) // 7688

// Scratch (no allocations allowed in kernel_launch)
__device__ float g_phi[NN];           // sigmoid(x_new)
__device__ float g_part[MM * SPLIT];  // H@Phi partial sums (chunk 0 folds win2)
__device__ int   g_cnt[MM];           // per-row H-chunk arrival counters (self-reset)

__device__ __forceinline__ float warp_sum(float v) {
#pragma unroll
    for (int o = 16; o > 0; o >>= 1) v += __shfl_xor_sync(0xffffffffu, v, o);
    return v;
}

__device__ __forceinline__ float sigmoidf(float v) {
    return 1.0f / (1.0f + expf(-v));
}

// ---------------------------------------------------------------------------
// Kernel 1 (kPre): 544 blocks x 256 threads. NO internal dependencies.
//   blocks [0, 32)   : x_new + g_phi (warp-per-row; hides under D stream)
//   blocks [32, 544) : W_new PARTIAL = (1-g)W + g*(D@psi) for rows [0,8192)
// ---------------------------------------------------------------------------
__global__ void __launch_bounds__(256) kPre(
    const float* __restrict__ x,    const float* __restrict__ W,
    const float* __restrict__ Win1, const float* __restrict__ I,
    const float* __restrict__ D,    const float* __restrict__ z,
    float* __restrict__ out_x, float* __restrict__ out_W) {

    __shared__ float s_vec[MM];
    int tid  = threadIdx.x;  // 256
    int warp = tid >> 5, lane = tid & 31;
    unsigned bid = blockIdx.x;

    if (bid < SETUP_BLKS) {
        // ================= setup: x_new + phi (8 rows/block) =================
        __shared__ float s_Ilo[256];
        s_vec[tid]       = sigmoidf(x[tid]);     // s_vec[0..255] = sigmoid(x)
        s_vec[tid + 256] = I[tid + 256];         // s_vec[256..511] = I hi half
        s_Ilo[tid] = I[tid];
        __syncthreads();

        int row = bid * 8 + warp;
        float a1 = 0.0f, a2 = 0.0f;
        const float* wr = W + (size_t)row * NN;
#pragma unroll
        for (int j = lane; j < NN; j += 32) a1 += wr[j] * s_vec[j];
        const float* w1 = Win1 + (size_t)row * KK;
#pragma unroll
        for (int k = lane; k < 256; k += 32) {
            a2 += w1[k] * s_Ilo[k] + w1[k + 256] * s_vec[k + 256];
        }
        a1 = warp_sum(a1);
        a2 = warp_sum(a2);
        if (lane == 0) {
            float xn = (1.0f - GAMMA) * x[row] + GAMMA * a1 + a2;
            out_x[row] = xn;
            g_phi[row] = sigmoidf(xn);
        }
    } else {
        // ========== W_new partial: 2 rows/warp D GEMV (no phi) ==========
        s_vec[tid]       = tanhf(z[tid]);
        s_vec[tid + 256] = tanhf(z[tid + 256]);
        __syncthreads();

        int p0 = (bid - SETUP_BLKS) * D_ROWS_PER_BLK + warp * 2;  // rows p0, p0+1
        const float4* dr0 = (const float4*)(D + (size_t)p0 * MM);
        const float4* dr1 = (const float4*)(D + (size_t)(p0 + 1) * MM);
        const float4* ps  = (const float4*)s_vec;

        float4 a0[4], a1[4];
#pragma unroll
        for (int q = 0; q < 4; q++) a0[q] = dr0[lane + 32 * q];  // 8 loads
#pragma unroll
        for (int q = 0; q < 4; q++) a1[q] = dr1[lane + 32 * q];  // in flight

        float acc0 = 0.0f, acc1 = 0.0f;
#pragma unroll
        for (int q = 0; q < 4; q++) {
            float4 s = ps[lane + 32 * q];
            acc0 += a0[q].x * s.x + a0[q].y * s.y + a0[q].z * s.z + a0[q].w * s.w;
            acc1 += a1[q].x * s.x + a1[q].y * s.y + a1[q].z * s.z + a1[q].w * s.w;
        }
        acc0 = warp_sum(acc0);
        acc1 = warp_sum(acc1);
        if (lane == 0) {
            out_W[p0]     = (1.0f - GAMMA) * W[p0]     + GAMMA * acc0;
            out_W[p0 + 1] = (1.0f - GAMMA) * W[p0 + 1] + GAMMA * acc1;
        }
    }
}

// ---------------------------------------------------------------------------
// Kernel 2 (kMain): 7688 blocks x 256 threads. phi ready via kernel boundary.
//   blocks [0, 8)        : Hebbian fixup for kPre rows [0, 8192)
//   blocks [8, 4104)     : H@Phi 32KB-chunk partials — conflict-free LDS
//   blocks [4104, 7688)  : D rows [8192, 65536) with Hebbian applied directly
// Near-1:1 D:H mix (R8's best-measured streaming ratio) + LDS-fixed H branch.
// ---------------------------------------------------------------------------
__global__ void __launch_bounds__(256) kMain(
    const float* __restrict__ W, const float* __restrict__ C,
    const float* __restrict__ D, const float* __restrict__ z,
    const float* __restrict__ H, const float* __restrict__ F,
    const float* __restrict__ Win2, const float* __restrict__ I,
    float* __restrict__ out_W, float* __restrict__ out_z) {

    __shared__ float s_vec[MM];   // psi(z) for D branch; phi for H/fixup branch
    __shared__ float s_phi[NN];   // phi (D branch Hebbian)
    __shared__ float s_red[8];
    int tid  = threadIdx.x;  // 256
    int warp = tid >> 5, lane = tid & 31;
    unsigned bid = blockIdx.x;

    if (bid < FIX_BLKS) {
        // ===== Hebbian fixup for kPre rows [0,8192): out_W += g*C*phi*phi =====
        s_vec[tid] = g_phi[tid];
        __syncthreads();
        int idx = bid * 256 + tid;   // float4 idx, 0..2047
        int p = idx * 4;             // < 8192
        int i = p >> 8;
        float pi = s_vec[i];
        float4 pj = ((const float4*)s_vec)[idx & 63];  // phi[j..j+3]
        float4 cc = ((const float4*)C)[idx];
        float4 w  = ((float4*)out_W)[idx];
        w.x += GAMMA * cc.x * pi * pj.x;
        w.y += GAMMA * cc.y * pi * pj.y;
        w.z += GAMMA * cc.z * pi * pj.z;
        w.w += GAMMA * cc.w * pi * pj.w;
        ((float4*)out_W)[idx] = w;
    } else if (bid < D_START) {
        // ========== H@Phi partial, 32 KB/block (+win2 on chunk 0) ==========
        int hIdx = bid - H_START;    // 0..4095
        s_vec[tid] = g_phi[tid];
        __syncthreads();

        int c = hIdx & (SPLIT - 1);  // chunk
        int m = hIdx >> 3;           // row
        const float4* hr = (const float4*)(H + (size_t)m * NN2 + (size_t)c * CHUNK);

        float4 h[8];
#pragma unroll
        for (int q = 0; q < 8; q++) h[q] = hr[tid + 256 * q];  // 8 in flight

        // Index algebra: p = c*8192 + 4*(tid + 256q)
        //   j = (4*tid) & 255        -> constant across q (one LDS.128)
        //   i = c*32 + (tid>>6) + 4q -> lane-uniform broadcast reads
        float4 pj = ((const float4*)s_vec)[tid & 63];
        int ibase = c * 32 + (tid >> 6);
        float acc = 0.0f;
#pragma unroll
        for (int q = 0; q < 8; q++) {
            float pi = s_vec[ibase + 4 * q];           // broadcast (N=1)
            acc += pi * (h[q].x * pj.x + h[q].y * pj.y +
                         h[q].z * pj.z + h[q].w * pj.w);
        }
        if (c == 0) {
            // fold (W_in_2 @ I)[m] into this chunk's partial
            const float* w2 = Win2 + (size_t)m * KK;
            acc += w2[tid] * I[tid] + w2[tid + 256] * I[tid + 256];
        }
        acc = warp_sum(acc);
        if (lane == 0) s_red[warp] = acc;
        __syncthreads();
        if (tid == 0) {
            float t = 0.0f;
#pragma unroll
            for (int w = 0; w < 8; w++) t += s_red[w];
            g_part[m * SPLIT + c] = t;
            __threadfence();                       // publish partial
            int old = atomicAdd(&g_cnt[m], 1);
            if (old == SPLIT - 1) {
                // last chunk of row m: combine (deterministic fixed order)
                g_cnt[m] = 0;                      // reset for next replay
                __threadfence();                   // acquire partials
                float s = 0.0f;
#pragma unroll
                for (int c2 = 0; c2 < SPLIT; c2++) s += g_part[m * SPLIT + c2];
                float zm  = z[m];
                float psi = tanhf(zm);
                out_z[m] = (1.0f - GAMMA * TAU) * zm +
                           (GAMMA * TAU) * (F[m] * psi + s);
            }
        }
    } else {
        // ========== D: 2 rows/warp GEMV + Hebbian (phi ready) ==========
        int dIdx = bid - D_START;    // 0..3583
        s_vec[tid]       = tanhf(z[tid]);
        s_vec[tid + 256] = tanhf(z[tid + 256]);
        s_phi[tid]       = g_phi[tid];
        __syncthreads();

        int p0 = PRE_D_ROWS + dIdx * D_ROWS_PER_BLK + warp * 2;
        const float4* dr0 = (const float4*)(D + (size_t)p0 * MM);
        const float4* dr1 = (const float4*)(D + (size_t)(p0 + 1) * MM);
        const float4* ps  = (const float4*)s_vec;

        float4 a0[4], a1[4];
#pragma unroll
        for (int q = 0; q < 4; q++) a0[q] = dr0[lane + 32 * q];
#pragma unroll
        for (int q = 0; q < 4; q++) a1[q] = dr1[lane + 32 * q];

        float acc0 = 0.0f, acc1 = 0.0f;
#pragma unroll
        for (int q = 0; q < 4; q++) {
            float4 s = ps[lane + 32 * q];
            acc0 += a0[q].x * s.x + a0[q].y * s.y + a0[q].z * s.z + a0[q].w * s.w;
            acc1 += a1[q].x * s.x + a1[q].y * s.y + a1[q].z * s.z + a1[q].w * s.w;
        }
        acc0 = warp_sum(acc0);
        acc1 = warp_sum(acc1);
        if (lane == 0) {
            int i = p0 >> 8;                 // p0 even => same i both rows
            int j0 = p0 & 255;
            float pi = s_phi[i];
            float ph0 = pi * s_phi[j0];
            float ph1 = pi * s_phi[j0 + 1];
            out_W[p0]     = (1.0f - GAMMA) * W[p0]
                          + GAMMA * (C[p0] * ph0 + acc0);
            out_W[p0 + 1] = (1.0f - GAMMA) * W[p0 + 1]
                          + GAMMA * (C[p0 + 1] * ph1 + acc1);
        }
    }
}

// ---------------------------------------------------------------------------
// Launch: inputs in metadata order: I, x, W, z, C, D, F, H, W_in_1, W_in_2.
// Output: concat(x_new[256], W_new[65536], z_new[512]) = 66304 floats.
// ---------------------------------------------------------------------------
extern "C" void kernel_launch(void* const* d_in, const int* in_sizes, int n_in,
                              void* d_out, int out_size) {
    const float* I    = (const float*)d_in[0];
    const float* x    = (const float*)d_in[1];
    const float* W    = (const float*)d_in[2];
    const float* z    = (const float*)d_in[3];
    const float* C    = (const float*)d_in[4];
    const float* D    = (const float*)d_in[5];
    const float* F    = (const float*)d_in[6];
    const float* H    = (const float*)d_in[7];
    const float* Win1 = (const float*)d_in[8];
    const float* Win2 = (const float*)d_in[9];

    float* out_x = (float*)d_out;            // [0, 256)
    float* out_W = out_x + NN;               // [256, 256+65536)
    float* out_z = out_W + NN2;              // [65792, 66304)

    // Kernel 1: x_new/phi setup hidden under a minimal phi-free D stream
    kPre<<<KPRE_BLKS, 256>>>(x, W, Win1, I, D, z, out_x, out_W);

    // Kernel 2: fixup + H stream (conflict-free LDS) + D stream (~1:1 mix)
    kMain<<<KMAIN_BLKS, 256>>>(W, C, D, z, H, F, Win2, I, out_W, out_z);
}

// round 15
// speedup vs baseline: 1.0080x; 1.0080x over previous
#include <cuda_runtime.h>

// Problem constants
#define GAMMA 0.1f
#define TAU   0.01f
#define NN    256          // neuron count
#define MM    512          // astrocyte count
#define KK    512          // input dim
#define NN2   (NN * NN)    // 65536
#define SPLIT 8            // chunks per H row (32 KB each)
#define CHUNK (NN2 / SPLIT) // 8192 floats per chunk

#define H_BLKS (MM * SPLIT)               // 4096
#define D_ROWS_PER_BLK 16
#define D_BLKS (NN2 / D_ROWS_PER_BLK)     // 4096

// Scratch (no allocations allowed in kernel_launch)
__device__ float g_phi[NN];           // sigmoid(x_new)
__device__ float g_part[MM * SPLIT];  // H@Phi partial sums (chunk 0 folds win2)
__device__ int   g_cnt[MM];           // per-row H-chunk arrival counters (self-reset)

__device__ __forceinline__ float warp_sum(float v) {
#pragma unroll
    for (int o = 16; o > 0; o >>= 1) v += __shfl_xor_sync(0xffffffffu, v, o);
    return v;
}

__device__ __forceinline__ float sigmoidf(float v) {
    return 1.0f / (1.0f + expf(-v));
}

// ---------------------------------------------------------------------------
// Kernel A (x-only): 256 blocks x 128 threads, block-per-row (R8's best-
// measured prelude: kA + launch gap = 4.3 us).
//   x_new[row] = (1-g)x[row] + g*(W[row,:]@sigmoid(x)) + Win1[row,:]@I
//   g_phi[row] = sigmoid(x_new[row])
// ---------------------------------------------------------------------------
__global__ void __launch_bounds__(128) kA(
    const float* __restrict__ x,    const float* __restrict__ W,
    const float* __restrict__ Win1, const float* __restrict__ I,
    float* __restrict__ out_x) {

    __shared__ float s_phi[NN];
    __shared__ float s_red[4];
    int tid  = threadIdx.x;  // 128
    int warp = tid >> 5, lane = tid & 31;

    s_phi[tid]       = sigmoidf(x[tid]);
    s_phi[tid + 128] = sigmoidf(x[tid + 128]);
    __syncthreads();

    int row = blockIdx.x;
    float a1 = 0.0f, a2 = 0.0f;
    if (tid < 64) {  // W row: 256 floats = 64 float4
        float4 w = ((const float4*)(W + (size_t)row * NN))[tid];
        float4 p = ((const float4*)s_phi)[tid];
        a1 = w.x * p.x + w.y * p.y + w.z * p.z + w.w * p.w;
    }
    {   // Win1 row: 512 floats = 128 float4; I direct (L2-hot, 2 KB)
        float4 a = ((const float4*)(Win1 + (size_t)row * KK))[tid];
        float4 b = ((const float4*)I)[tid];
        a2 = a.x * b.x + a.y * b.y + a.z * b.z + a.w * b.w;
    }
    float v = GAMMA * a1 + a2;

    v = warp_sum(v);
    if (lane == 0) s_red[warp] = v;
    __syncthreads();
    if (tid == 0) {
        float t = s_red[0] + s_red[1] + s_red[2] + s_red[3];
        float xn = (1.0f - GAMMA) * x[row] + t;
        out_x[row] = xn;
        g_phi[row] = sigmoidf(xn);
    }
}

// ---------------------------------------------------------------------------
// Kernel B: 8192 blocks x 256 threads. phi ready via kernel boundary.
//   blocks [0, 4096)    : H@Phi 32KB-chunk partials — CONFLICT-FREE LDS
//                         (one LDS.128 reused across 8 iters + 8 broadcasts).
//                         Chunk 0 folds (W_in_2@I)[m]. Last chunk per row
//                         combines the 8 partials into z_new.
//   blocks [4096, 8192) : W_new full rows (D GEMV + Hebbian), 2 rows/warp.
// R8's H-then-D 1:1 ordering — best measured streaming mix (6333 GB/s).
// ---------------------------------------------------------------------------
__global__ void __launch_bounds__(256) kB(
    const float* __restrict__ W, const float* __restrict__ C,
    const float* __restrict__ D, const float* __restrict__ z,
    const float* __restrict__ H, const float* __restrict__ F,
    const float* __restrict__ Win2, const float* __restrict__ I,
    float* __restrict__ out_W, float* __restrict__ out_z) {

    __shared__ float s_vec[MM];   // psi(z) for D branch; phi for H branch
    __shared__ float s_phi[NN];   // phi (D branch Hebbian)
    __shared__ float s_red[8];
    int tid  = threadIdx.x;  // 256
    int warp = tid >> 5, lane = tid & 31;
    unsigned bid = blockIdx.x;

    if (bid < H_BLKS) {
        // ========== H@Phi partial, 32 KB/block (+win2 on chunk 0) ==========
        s_vec[tid] = g_phi[tid];
        __syncthreads();

        int c = bid & (SPLIT - 1);  // chunk
        int m = bid >> 3;           // row
        const float4* hr = (const float4*)(H + (size_t)m * NN2 + (size_t)c * CHUNK);

        float4 h[8];
#pragma unroll
        for (int q = 0; q < 8; q++) h[q] = hr[tid + 256 * q];  // 8 in flight

        // Index algebra: p = c*8192 + 4*(tid + 256q)
        //   j = (4*tid) & 255        -> constant across q (one LDS.128)
        //   i = c*32 + (tid>>6) + 4q -> lane-uniform broadcast reads
        float4 pj = ((const float4*)s_vec)[tid & 63];
        int ibase = c * 32 + (tid >> 6);
        float acc = 0.0f;
#pragma unroll
        for (int q = 0; q < 8; q++) {
            float pi = s_vec[ibase + 4 * q];           // broadcast (N=1)
            acc += pi * (h[q].x * pj.x + h[q].y * pj.y +
                         h[q].z * pj.z + h[q].w * pj.w);
        }
        if (c == 0) {
            // fold (W_in_2 @ I)[m] into this chunk's partial
            const float* w2 = Win2 + (size_t)m * KK;
            acc += w2[tid] * I[tid] + w2[tid + 256] * I[tid + 256];
        }
        acc = warp_sum(acc);
        if (lane == 0) s_red[warp] = acc;
        __syncthreads();
        if (tid == 0) {
            float t = 0.0f;
#pragma unroll
            for (int w = 0; w < 8; w++) t += s_red[w];
            g_part[m * SPLIT + c] = t;
            __threadfence();                       // publish partial
            int old = atomicAdd(&g_cnt[m], 1);
            if (old == SPLIT - 1) {
                // last chunk of row m: combine (deterministic fixed order)
                g_cnt[m] = 0;                      // reset for next replay
                __threadfence();                   // acquire partials
                float s = 0.0f;
#pragma unroll
                for (int c2 = 0; c2 < SPLIT; c2++) s += g_part[m * SPLIT + c2];
                float zm  = z[m];
                float psi = tanhf(zm);
                out_z[m] = (1.0f - GAMMA * TAU) * zm +
                           (GAMMA * TAU) * (F[m] * psi + s);
            }
        }
    } else {
        // ========== D: 2 rows/warp GEMV + Hebbian (phi ready) ==========
        int dIdx = bid - H_BLKS;     // 0..4095
        s_vec[tid]       = tanhf(z[tid]);
        s_vec[tid + 256] = tanhf(z[tid + 256]);
        s_phi[tid]       = g_phi[tid];
        __syncthreads();

        int p0 = dIdx * D_ROWS_PER_BLK + warp * 2;   // rows p0, p0+1
        const float4* dr0 = (const float4*)(D + (size_t)p0 * MM);
        const float4* dr1 = (const float4*)(D + (size_t)(p0 + 1) * MM);
        const float4* ps  = (const float4*)s_vec;

        float4 a0[4], a1[4];
#pragma unroll
        for (int q = 0; q < 4; q++) a0[q] = dr0[lane + 32 * q];
#pragma unroll
        for (int q = 0; q < 4; q++) a1[q] = dr1[lane + 32 * q];

        float acc0 = 0.0f, acc1 = 0.0f;
#pragma unroll
        for (int q = 0; q < 4; q++) {
            float4 s = ps[lane + 32 * q];
            acc0 += a0[q].x * s.x + a0[q].y * s.y + a0[q].z * s.z + a0[q].w * s.w;
            acc1 += a1[q].x * s.x + a1[q].y * s.y + a1[q].z * s.z + a1[q].w * s.w;
        }
        acc0 = warp_sum(acc0);
        acc1 = warp_sum(acc1);
        if (lane == 0) {
            int i = p0 >> 8;                 // p0 even => same i both rows
            int j0 = p0 & 255;
            float pi = s_phi[i];
            float ph0 = pi * s_phi[j0];
            float ph1 = pi * s_phi[j0 + 1];
            out_W[p0]     = (1.0f - GAMMA) * W[p0]
                          + GAMMA * (C[p0] * ph0 + acc0);
            out_W[p0 + 1] = (1.0f - GAMMA) * W[p0 + 1]
                          + GAMMA * (C[p0 + 1] * ph1 + acc1);
        }
    }
}

// ---------------------------------------------------------------------------
// Launch: inputs in metadata order: I, x, W, z, C, D, F, H, W_in_1, W_in_2.
// Output: concat(x_new[256], W_new[65536], z_new[512]) = 66304 floats.
// ---------------------------------------------------------------------------
extern "C" void kernel_launch(void* const* d_in, const int* in_sizes, int n_in,
                              void* d_out, int out_size) {
    const float* I    = (const float*)d_in[0];
    const float* x    = (const float*)d_in[1];
    const float* W    = (const float*)d_in[2];
    const float* z    = (const float*)d_in[3];
    const float* C    = (const float*)d_in[4];
    const float* D    = (const float*)d_in[5];
    const float* F    = (const float*)d_in[6];
    const float* H    = (const float*)d_in[7];
    const float* Win1 = (const float*)d_in[8];
    const float* Win2 = (const float*)d_in[9];

    float* out_x = (float*)d_out;            // [0, 256)
    float* out_W = out_x + NN;               // [256, 256+65536)
    float* out_z = out_W + NN2;              // [65792, 66304)

    // Stage 1: x_new + phi only (0.78 MB, 256 blocks — cheapest prelude)
    kA<<<NN, 128>>>(x, W, Win1, I, out_x);

    // Stage 2: full H stream (conflict-free LDS, win2 fold, z tail) + full D
    kB<<<H_BLKS + D_BLKS, 256>>>(W, C, D, z, H, F, Win2, I, out_W, out_z);
}